// round 2
// baseline (speedup 1.0000x reference)
#include <cuda_runtime.h>
#include <math.h>

// Shapes: N=1024 nodes, IN=128, H=8 heads, F=16 hidden, out = [1024,128] f32.

__device__ float d_WT[128*128];          // W transposed: WT[k][t] = W[t][k]
__device__ float d_gT[128*1024];         // gT[(h*16+f)*1024 + j] = g[j,h,f]
__device__ float d_src[1024*8];
__device__ float d_dst[1024*8];
__device__ float d_w[8*1024*1024];       // w[h][i][j]  (32 MB)

// ---------------------------------------------------------------- kernel A0
__global__ void k_transposeW(const float* __restrict__ W) {
    int idx = blockIdx.x * 1024 + threadIdx.x;          // 16384 total
    d_WT[(idx & 127) * 128 + (idx >> 7)] = W[idx];
}

// ---------------------------------------------------------------- kernel A
// One block per node row: g row (128 outputs) + src/dst per head.
__global__ void __launch_bounds__(128) k_proj(const float* __restrict__ h,
                                              const float* __restrict__ attn_w) {
    int i = blockIdx.x, t = threadIdx.x;
    __shared__ float hrow[128];
    hrow[t] = h[i * 128 + t];
    __syncthreads();
    float acc = 0.f;
    #pragma unroll 8
    for (int k = 0; k < 128; ++k)
        acc = fmaf(hrow[k], d_WT[k * 128 + t], acc);    // coalesced, L1-resident
    d_gT[t * 1024 + i] = acc;

    int f = t & 15;
    float vs = acc * attn_w[f];
    float vd = acc * attn_w[16 + f];
    #pragma unroll
    for (int o = 8; o; o >>= 1) {
        vs += __shfl_down_sync(0xffffffffu, vs, o, 16);
        vd += __shfl_down_sync(0xffffffffu, vd, o, 16);
    }
    if (f == 0) {
        d_src[i * 8 + (t >> 4)] = vs;
        d_dst[i * 8 + (t >> 4)] = vd;
    }
}

// ---------------------------------------------------------------- kernel B
// One block (256 thr) per row i: dual softmax chain -> attention weights w.
__device__ __forceinline__ int SW(int idx) { return idx ^ ((idx >> 5) & 7); }

__device__ __forceinline__ float blockReduce(float v, float* red, bool isMax) {
    int tid = threadIdx.x, lane = tid & 31, warp = tid >> 5;
    __syncthreads();                                    // protect red reuse
    #pragma unroll
    for (int o = 16; o; o >>= 1) {
        float u = __shfl_xor_sync(0xffffffffu, v, o);
        v = isMax ? fmaxf(v, u) : v + u;
    }
    if (lane == 0) red[warp] = v;
    __syncthreads();
    if (tid == 0) {
        float a = red[0];
        for (int w = 1; w < 8; ++w) a = isMax ? fmaxf(a, red[w]) : a + red[w];
        red[0] = a;
    }
    __syncthreads();
    return red[0];
}

// per-head reduction: thread's head = tid&7; results broadcast via outArr[8]
__device__ __forceinline__ float headReduce(float v, float* red, bool isMax,
                                            float* outArr) {
    int tid = threadIdx.x, lane = tid & 31, warp = tid >> 5;
    __syncthreads();
    {   float u = __shfl_xor_sync(0xffffffffu, v, 8);
        v = isMax ? fmaxf(v, u) : v + u;
        u = __shfl_xor_sync(0xffffffffu, v, 16);
        v = isMax ? fmaxf(v, u) : v + u; }
    if (lane < 8) red[warp * 8 + lane] = v;
    __syncthreads();
    if (tid < 8) {
        float a = red[tid];
        for (int w = 1; w < 8; ++w)
            a = isMax ? fmaxf(a, red[w * 8 + tid]) : a + red[w * 8 + tid];
        outArr[tid] = a;
    }
    __syncthreads();
    return outArr[tid & 7];
}

__global__ void __launch_bounds__(256) k_attn(const float* __restrict__ s,
                                              const int* __restrict__ adj) {
    __shared__ float ep[8192];     // [j*8+h] XOR-swizzled, reused e -> p -> u
    __shared__ float sq[1024];     // masked s row, then exp(s-ms)
    __shared__ float red[64];
    __shared__ float zt_arr[8], m_arr[8], z_arr[8];

    int i = blockIdx.x, tid = threadIdx.x;
    const float NEG = -INFINITY;

    // stage masked s row + its max
    float smax = NEG;
    for (int j = tid; j < 1024; j += 256) {
        float sv = s[i * 1024 + j];
        sv = adj[i * 1024 + j] ? sv : NEG;
        sq[j] = sv;
        smax = fmaxf(smax, sv);
    }
    float m_s = blockReduce(smax, red, true);   // barrier also publishes sq

    int h = tid & 7;
    float srcv = d_src[i * 8 + h];

    // pass 1: e = masked lrelu(src+dst), track per-head max
    float m = NEG;
    #pragma unroll 4
    for (int it = 0; it < 32; ++it) {
        int idx = tid + 256 * it;           // == j*8 + h
        int j = idx >> 3;
        float e = srcv + d_dst[idx];
        e = e > 0.f ? e : 0.2f * e;
        if (sq[j] == NEG) e = NEG;
        ep[SW(idx)] = e;
        m = fmaxf(m, e);
    }
    float m_e = headReduce(m, red, true, m_arr);

    // pass 2: p = exp(e - m_e), Z_e ; and s' numerators, Z_s
    float z = 0.f;
    #pragma unroll 4
    for (int it = 0; it < 32; ++it) {
        int idx = tid + 256 * it;
        float p = __expf(ep[SW(idx)] - m_e);
        ep[SW(idx)] = p;
        z += p;
    }
    float z_e = headReduce(z, red, false, z_arr);
    float zs = 0.f;
    for (int j = tid; j < 1024; j += 256) {
        float qv = __expf(sq[j] - m_s);
        sq[j] = qv;
        zs += qv;
    }
    float z_s = blockReduce(zs, red, false);
    float inva = 1.0f / z_e, invs = 1.0f / z_s;

    // pass 3: t = a + s' in [0,2] -> u = exp(t) (no max needed), Z_t
    float zt = 0.f;
    #pragma unroll 4
    for (int it = 0; it < 32; ++it) {
        int idx = tid + 256 * it;
        int j = idx >> 3;
        float t = ep[SW(idx)] * inva + sq[j] * invs;
        float u = __expf(t);
        ep[SW(idx)] = u;
        zt += u;
    }
    headReduce(zt, red, false, zt_arr);

    // pass 4: head-major coalesced store of w[h][i][j]
    int h2 = tid >> 5, l = tid & 31;
    float invzt = 1.0f / zt_arr[h2];
    #pragma unroll 4
    for (int it = 0; it < 32; ++it) {
        int j = l + 32 * it;
        float wv = ep[SW(j * 8 + h2)] * invzt;   // swizzle keeps this conflict-free
        d_w[h2 * 1048576 + i * 1024 + j] = wv;
    }
}

// ---------------------------------------------------------------- kernel C
// out[i, h*16+f] += sum_j w[h][i][j] * gT[h][f][j]
// grid (4 j-splits, 8 i-tiles, 8 heads), 64 threads, 8i x 4f register tile.
__global__ void __launch_bounds__(64) k_out(float* __restrict__ out) {
    int js = blockIdx.x, it = blockIdx.y, h = blockIdx.z;
    int i0 = it * 128, j0 = js * 256;
    __shared__ float ws[128 * 36];   // 32 j + pad(4) -> conflict-free float4
    __shared__ float gs[16 * 36];

    int tid = threadIdx.x;
    int fg = tid >> 4;               // 0..3
    int ig = tid & 15;               // 0..15
    float acc[8][4] = {};

    const float* wbase = d_w + h * 1048576 + i0 * 1024 + j0;
    const float* gbase = d_gT + h * 16384 + j0;

    for (int ph = 0; ph < 8; ++ph) {
        int jb = ph * 32;
        __syncthreads();
        // stage w chunk [128 x 32]
        #pragma unroll
        for (int rr = 0; rr < 2; ++rr) {
            int row = tid * 2 + rr;
            const float4* s4 = (const float4*)(wbase + row * 1024 + jb);
            #pragma unroll
            for (int c = 0; c < 8; ++c)
                *(float4*)(ws + row * 36 + c * 4) = s4[c];
        }
        // stage g chunk [16 x 32]
        {
            int f = tid >> 2, c = tid & 3;
            const float* gp = gbase + f * 1024 + jb;
            *(float4*)(gs + f * 36 + c * 4)       = *(const float4*)(gp + c * 4);
            *(float4*)(gs + f * 36 + (c + 4) * 4) = *(const float4*)(gp + (c + 4) * 4);
        }
        __syncthreads();
        #pragma unroll
        for (int step = 0; step < 8; ++step) {
            int jo = step * 4;
            float4 gv[4];
            #pragma unroll
            for (int c2 = 0; c2 < 4; ++c2)
                gv[c2] = *(float4*)(gs + (fg + 4 * c2) * 36 + jo);
            #pragma unroll
            for (int r = 0; r < 8; ++r) {
                float4 wv = *(float4*)(ws + (ig + 16 * r) * 36 + jo);
                #pragma unroll
                for (int c2 = 0; c2 < 4; ++c2) {
                    acc[r][c2] = fmaf(wv.x, gv[c2].x, acc[r][c2]);
                    acc[r][c2] = fmaf(wv.y, gv[c2].y, acc[r][c2]);
                    acc[r][c2] = fmaf(wv.z, gv[c2].z, acc[r][c2]);
                    acc[r][c2] = fmaf(wv.w, gv[c2].w, acc[r][c2]);
                }
            }
        }
    }
    #pragma unroll
    for (int r = 0; r < 8; ++r)
        #pragma unroll
        for (int c2 = 0; c2 < 4; ++c2) {
            int i = i0 + ig + 16 * r;
            int col = h * 16 + fg + 4 * c2;
            atomicAdd(&out[i * 128 + col], acc[r][c2]);
        }
}

// ---------------------------------------------------------------- launch
extern "C" void kernel_launch(void* const* d_in, const int* in_sizes, int n_in,
                              void* d_out, int out_size) {
    const float* h   = (const float*)d_in[0];
    const int*   adj = (const int*)  d_in[1];
    const float* s   = (const float*)d_in[2];
    const float* W   = (const float*)d_in[3];
    const float* aw  = (const float*)d_in[4];
    float* out = (float*)d_out;

    k_transposeW<<<16, 1024>>>(W);
    k_proj<<<1024, 128>>>(h, aw);
    k_attn<<<1024, 256>>>(s, adj);
    cudaMemsetAsync(out, 0, (size_t)out_size * sizeof(float));
    k_out<<<dim3(4, 8, 8), 64>>>(out);
}

// round 4
// speedup vs baseline: 1.0762x; 1.0762x over previous
#include <cuda_runtime.h>
#include <math.h>

// Shapes: N=1024 nodes, IN=128, H=8 heads, F=16 hidden, out = [1024,128] f32.

__device__ float d_gT[128*1024];         // gT[(h*16+f)*1024 + j] = g[j,h,f]
__device__ float d_src[1024*8];
__device__ float d_dst[1024*8];
__device__ float d_w[8*1024*1024];       // unnormalized u[h][i][j]  (32 MB)
__device__ float d_zt[1024*8];           // Z_t[i][h]

// packed f32x2 FMA: d = a*b + d (two independent fp32 FMAs per instruction)
#define FMA2(acc, a, b) \
    asm("fma.rn.f32x2 %0, %1, %2, %0;" : "+l"(acc) : "l"(a), "l"(b))

// ---------------------------------------------------------------- kernel A
// 8 rows per block, 128 threads. Reads W directly (k-contiguous), amortized 8x.
__global__ void __launch_bounds__(128) k_proj(const float* __restrict__ hin,
                                              const float* __restrict__ W,
                                              const float* __restrict__ aw) {
    int i0 = blockIdx.x * 8, t = threadIdx.x;
    __shared__ float hs[8][128];
    #pragma unroll
    for (int r = 0; r < 8; ++r) hs[r][t] = hin[(i0 + r) * 128 + t];
    __syncthreads();

    float acc[8] = {};
    #pragma unroll 4
    for (int k4 = 0; k4 < 32; ++k4) {
        float4 wq = *(const float4*)(W + t * 128 + k4 * 4);
        #pragma unroll
        for (int r = 0; r < 8; ++r) {
            float4 hq = *(const float4*)(&hs[r][k4 * 4]);   // broadcast LDS.128
            acc[r] = fmaf(wq.x, hq.x, acc[r]);
            acc[r] = fmaf(wq.y, hq.y, acc[r]);
            acc[r] = fmaf(wq.z, hq.z, acc[r]);
            acc[r] = fmaf(wq.w, hq.w, acc[r]);
        }
    }
    // gT[t][i0..i0+7] : two STG.128
    *(float4*)(d_gT + t * 1024 + i0)     = make_float4(acc[0], acc[1], acc[2], acc[3]);
    *(float4*)(d_gT + t * 1024 + i0 + 4) = make_float4(acc[4], acc[5], acc[6], acc[7]);

    int f = t & 15, hd = t >> 4;
    float as = aw[f], ad = aw[16 + f];
    #pragma unroll
    for (int r = 0; r < 8; ++r) {
        float vs = acc[r] * as, vd = acc[r] * ad;
        #pragma unroll
        for (int o = 8; o; o >>= 1) {
            vs += __shfl_down_sync(0xffffffffu, vs, o, 16);
            vd += __shfl_down_sync(0xffffffffu, vd, o, 16);
        }
        if (f == 0) {
            d_src[(i0 + r) * 8 + hd] = vs;
            d_dst[(i0 + r) * 8 + hd] = vd;
        }
    }
}

// ---------------------------------------------------------------- kernel B
__device__ __forceinline__ int SW(int idx) { return idx ^ ((idx >> 5) & 7); }

__device__ __forceinline__ float blockReduce(float v, float* red, bool isMax) {
    int tid = threadIdx.x, lane = tid & 31, warp = tid >> 5;
    __syncthreads();
    #pragma unroll
    for (int o = 16; o; o >>= 1) {
        float u = __shfl_xor_sync(0xffffffffu, v, o);
        v = isMax ? fmaxf(v, u) : v + u;
    }
    if (lane == 0) red[warp] = v;
    __syncthreads();
    if (tid == 0) {
        float a = red[0];
        for (int w = 1; w < 8; ++w) a = isMax ? fmaxf(a, red[w]) : a + red[w];
        red[0] = a;
    }
    __syncthreads();
    return red[0];
}

// per-head reduction: thread's head = tid&7
__device__ __forceinline__ float headReduce(float v, float* red, float* outArr) {
    int tid = threadIdx.x, lane = tid & 31, warp = tid >> 5;
    __syncthreads();
    v += __shfl_xor_sync(0xffffffffu, v, 8);
    v += __shfl_xor_sync(0xffffffffu, v, 16);
    if (lane < 8) red[warp * 8 + lane] = v;
    __syncthreads();
    if (tid < 8) {
        float a = red[tid];
        for (int w = 1; w < 8; ++w) a += red[w * 8 + tid];
        outArr[tid] = a;
    }
    __syncthreads();
    return outArr[tid & 7];
}

// One block (256 thr) per row i. 3 sweeps:
//  stage: masked s + m_s + per-head masked max(dst)  [m_e via lrelu monotonicity]
//  pass2: p = exp(e - m_e), Z_e ; q = exp(s - m_s), Z_s
//  pass3: u = exp(p/Z_e + q/Z_s) -> gmem (unnormalized), Z_t -> d_zt
__global__ void __launch_bounds__(256) k_attn(const float* __restrict__ s,
                                              const int* __restrict__ adj) {
    __shared__ float ep[8192];     // p values, [j*8+h] XOR-swizzled
    __shared__ float sq[1024];     // masked s, then q = exp(s - m_s)
    __shared__ float red[64];
    __shared__ float m_arr[8], z_arr[8];

    int i = blockIdx.x, tid = threadIdx.x;
    int lane = tid & 31, warp = tid >> 5;
    const float NEG = -INFINITY;

    // ---- stage: masked s + smax + masked per-head dst max (vectorized) ----
    int j0 = tid * 4;
    float4 sv4 = *(const float4*)(s + i * 1024 + j0);
    int4  av4 = *(const int4*)(adj + i * 1024 + j0);
    float svs[4] = {sv4.x, sv4.y, sv4.z, sv4.w};
    int   avs[4] = {av4.x, av4.y, av4.z, av4.w};

    float md[8];
    #pragma unroll
    for (int h = 0; h < 8; ++h) md[h] = NEG;
    float smax = NEG;
    #pragma unroll
    for (int e = 0; e < 4; ++e) {
        float sv = avs[e] ? svs[e] : NEG;
        sq[j0 + e] = sv;
        smax = fmaxf(smax, sv);
        if (avs[e]) {
            float4 d0 = *(const float4*)(d_dst + (j0 + e) * 8);
            float4 d1 = *(const float4*)(d_dst + (j0 + e) * 8 + 4);
            md[0] = fmaxf(md[0], d0.x); md[1] = fmaxf(md[1], d0.y);
            md[2] = fmaxf(md[2], d0.z); md[3] = fmaxf(md[3], d0.w);
            md[4] = fmaxf(md[4], d1.x); md[5] = fmaxf(md[5], d1.y);
            md[6] = fmaxf(md[6], d1.z); md[7] = fmaxf(md[7], d1.w);
        }
    }
    float m_s = blockReduce(smax, red, true);

    // reduce md[8] across block -> m_e = lrelu(src + maxdst)
    #pragma unroll
    for (int o = 16; o; o >>= 1)
        #pragma unroll
        for (int h = 0; h < 8; ++h)
            md[h] = fmaxf(md[h], __shfl_xor_sync(0xffffffffu, md[h], o));
    __syncthreads();                      // protect red reuse
    if (lane == 0)
        #pragma unroll
        for (int h = 0; h < 8; ++h) red[warp * 8 + h] = md[h];
    __syncthreads();
    if (tid < 8) {
        float a = red[tid];
        for (int w = 1; w < 8; ++w) a = fmaxf(a, red[w * 8 + tid]);
        float v = d_src[i * 8 + tid] + a;
        m_arr[tid] = v > 0.f ? v : 0.2f * v;          // lrelu monotone -> max
    }
    __syncthreads();

    // ---- pass2: p + Z_e ----
    int h = tid & 7;
    float m_e  = m_arr[h];
    float srcv = d_src[i * 8 + h];
    float z = 0.f;
    #pragma unroll 4
    for (int it = 0; it < 32; ++it) {
        int idx = tid + 256 * it;          // == j*8 + h
        int j = idx >> 3;
        float e = srcv + d_dst[idx];
        e = e > 0.f ? e : 0.2f * e;
        float p = (sq[j] == NEG) ? 0.f : __expf(e - m_e);
        ep[SW(idx)] = p;
        z += p;
    }
    headReduce(z, red, z_arr);

    // ---- q + Z_s (each thread owns its 4 j's) ----
    float zs = 0.f;
    #pragma unroll
    for (int e = 0; e < 4; ++e) {
        float qv = __expf(sq[j0 + e] - m_s);
        sq[j0 + e] = qv;
        zs += qv;
    }
    float z_s = blockReduce(zs, red, false);
    float invs = 1.0f / z_s;

    // ---- pass3: u = exp(a + s') (unnormalized), coalesced store + Z_t ----
    int h2 = tid >> 5;
    float inva = 1.0f / z_arr[h2];
    float* wrow = d_w + h2 * 1048576 + i * 1024;
    float zt = 0.f;
    #pragma unroll 4
    for (int it = 0; it < 32; ++it) {
        int j = lane + 32 * it;
        float p = ep[SW(j * 8 + h2)];                 // conflict-free via swizzle
        float u = __expf(fmaf(p, inva, sq[j] * invs));
        wrow[j] = u;
        zt += u;
    }
    #pragma unroll
    for (int o = 16; o; o >>= 1) zt += __shfl_xor_sync(0xffffffffu, zt, o);
    if (lane == 0) d_zt[i * 8 + h2] = zt;
}

// ---------------------------------------------------------------- kernel C
// out[i, h*16+f] = (1/Z_t[i,h]) * sum_j u[h][i][j] * gT[h*16+f][j]
// grid (4 j-splits, 8 i-tiles, 8 heads), 256 threads, 8i x 1f per thread,
// j packed pairwise into fma.rn.f32x2.
__global__ void __launch_bounds__(256) k_out(float* __restrict__ out) {
    int js = blockIdx.x, it = blockIdx.y, h = blockIdx.z;
    int i0 = it * 128, j0 = js * 256;
    __shared__ float ws[128 * 36];   // [i][32 j] pad->36: conflict-free f4
    __shared__ float gs[16 * 36];

    int tid = threadIdx.x;
    int f = tid & 15, isub = tid >> 4;          // isub 0..15, 8 rows each
    int srow = tid >> 3, sc4 = tid & 7;
    unsigned long long acc2[8] = {};            // (even-j, odd-j) partials

    const float* wbase = d_w + h * 1048576 + i0 * 1024 + j0;
    const float* gbase = d_gT + (h * 16) * 1024 + j0;

    for (int ph = 0; ph < 8; ++ph) {
        int jb = ph * 32;
        __syncthreads();
        #pragma unroll
        for (int q = 0; q < 4; ++q) {
            int row = srow + 32 * q;
            *(float4*)(ws + row * 36 + sc4 * 4) =
                *(const float4*)(wbase + row * 1024 + jb + sc4 * 4);
        }
        if (tid < 128) {
            int fr = tid >> 3;
            *(float4*)(gs + fr * 36 + sc4 * 4) =
                *(const float4*)(gbase + fr * 1024 + jb + sc4 * 4);
        }
        __syncthreads();

        unsigned long long gv[16];
        #pragma unroll
        for (int j4 = 0; j4 < 8; ++j4) {
            ulonglong2 g2 = *(ulonglong2*)(gs + f * 36 + j4 * 4);
            gv[2 * j4]     = g2.x;
            gv[2 * j4 + 1] = g2.y;
        }
        #pragma unroll
        for (int r = 0; r < 8; ++r) {
            const float* wr = ws + (isub * 8 + r) * 36;
            #pragma unroll
            for (int j4 = 0; j4 < 8; ++j4) {
                ulonglong2 w2 = *(ulonglong2*)(wr + j4 * 4);
                FMA2(acc2[r], w2.x, gv[2 * j4]);
                FMA2(acc2[r], w2.y, gv[2 * j4 + 1]);
            }
        }
    }

    #pragma unroll
    for (int r = 0; r < 8; ++r) {
        int i = i0 + isub * 8 + r;
        float lo = __uint_as_float((unsigned)acc2[r]);
        float hi = __uint_as_float((unsigned)(acc2[r] >> 32));
        float v = (lo + hi) / d_zt[i * 8 + h];
        atomicAdd(&out[i * 128 + h * 16 + f], v);
    }
}

// ---------------------------------------------------------------- launch
extern "C" void kernel_launch(void* const* d_in, const int* in_sizes, int n_in,
                              void* d_out, int out_size) {
    const float* h   = (const float*)d_in[0];
    const int*   adj = (const int*)  d_in[1];
    const float* s   = (const float*)d_in[2];
    const float* W   = (const float*)d_in[3];
    const float* aw  = (const float*)d_in[4];
    float* out = (float*)d_out;

    k_proj<<<128, 128>>>(h, W, aw);
    k_attn<<<1024, 256>>>(s, adj);
    cudaMemsetAsync(out, 0, (size_t)out_size * sizeof(float));
    k_out<<<dim3(4, 8, 8), 256>>>(out);
}